// round 1
// baseline (speedup 1.0000x reference)
#include <cuda_runtime.h>
#include <cstdint>

#define D 128
#define MAXN 50000
#define MAXE 800000

// ---------------- scratch (device globals; no allocations allowed) ----------
__device__ float g_AX[MAXN * D];
__device__ float g_BX[MAXN * D];
__device__ float g_DX[MAXN * D];
__device__ float g_EX[MAXN * D];
__device__ float g_num[MAXN * D];
__device__ float g_den[MAXN * D];
__device__ float g_H  [MAXN * D];
__device__ float g_deg[MAXN];
__device__ float g_colsum[D];
__device__ float g_colsq [D];
__device__ float g_scale [D];
__device__ float g_shift [D];

// ---------------- helpers ----------------------------------------------------
__device__ __forceinline__ void red_add_v4(float* p, float4 v) {
    asm volatile("red.global.add.v4.f32 [%0], {%1, %2, %3, %4};"
                 :: "l"(p), "f"(v.x), "f"(v.y), "f"(v.z), "f"(v.w)
                 : "memory");
}

__device__ __forceinline__ float sigmoidf_fast(float x) {
    return 1.0f / (1.0f + __expf(-x));
}

// ---------------- kernel 0: zero accumulators --------------------------------
__global__ void zero_kernel(int n) {
    int tid = blockIdx.x * blockDim.x + threadIdx.x;
    int stride = gridDim.x * blockDim.x;
    int total = n * D;
    for (int i = tid; i < total; i += stride) {
        g_num[i] = 0.0f;
        g_den[i] = 0.0f;
    }
    for (int i = tid; i < n; i += stride) g_deg[i] = 0.0f;
    if (tid < D) { g_colsum[tid] = 0.0f; g_colsq[tid] = 0.0f; }
}

// ---------------- kernel 1: fused 4-way GEMM  Y = X @ W + b ------------------
// blockIdx.y in {0,1,2,3} selects (W_A->g_AX, W_B->g_BX, W_D->g_DX, W_E->g_EX)
// BM=64 rows, BN=128 cols (full), BK=128 (full). 256 threads, 8x4 acc/thread.
// Dynamic smem: Xs[64][128] (32KB) + Ws[128][128] (64KB) = 96KB.
__global__ __launch_bounds__(256) void gemm4_kernel(
    const float* __restrict__ X,
    const float* __restrict__ W_A, const float* __restrict__ b_A,
    const float* __restrict__ W_B, const float* __restrict__ b_B,
    const float* __restrict__ W_D, const float* __restrict__ b_D,
    const float* __restrict__ W_E, const float* __restrict__ b_E,
    int n)
{
    extern __shared__ float smem[];
    float* Xs = smem;          // [64][128]
    float* Ws = smem + 64 * D; // [128][128]

    const float* W; const float* b; float* Y;
    switch (blockIdx.y) {
        case 0:  W = W_A; b = b_A; Y = g_AX; break;
        case 1:  W = W_B; b = b_B; Y = g_BX; break;
        case 2:  W = W_D; b = b_D; Y = g_DX; break;
        default: W = W_E; b = b_E; Y = g_EX; break;
    }

    const int tid  = threadIdx.x;
    const int tx   = tid & 31;   // col group: cols tx*4 .. tx*4+3
    const int ty   = tid >> 5;   // row group: rows ty*8 .. ty*8+7
    const int row0 = blockIdx.x * 64;

    // Load W tile: 128x128 floats = 4096 float4
    {
        const float4* Wg = reinterpret_cast<const float4*>(W);
        float4* Ws4 = reinterpret_cast<float4*>(Ws);
        #pragma unroll
        for (int i = 0; i < 16; i++) {
            int f = tid + i * 256;      // f in [0,4096)
            Ws4[f] = Wg[f];
        }
    }
    // Load X tile: 64x128 floats = 2048 float4 (guard rows)
    {
        const float4* Xg = reinterpret_cast<const float4*>(X);
        float4* Xs4 = reinterpret_cast<float4*>(Xs);
        #pragma unroll
        for (int i = 0; i < 8; i++) {
            int f   = tid + i * 256;    // f in [0,2048)
            int r   = f >> 5;           // local row
            int k4  = f & 31;           // float4 index within row
            int gr  = row0 + r;
            float4 v = make_float4(0.f, 0.f, 0.f, 0.f);
            if (gr < n) v = Xg[gr * (D / 4) + k4];
            Xs4[r * (D / 4) + k4] = v;
        }
    }
    __syncthreads();

    float acc[8][4];
    #pragma unroll
    for (int r = 0; r < 8; r++)
        #pragma unroll
        for (int j = 0; j < 4; j++) acc[r][j] = 0.0f;

    #pragma unroll 4
    for (int k = 0; k < D; k++) {
        float4 w = reinterpret_cast<const float4*>(&Ws[k * D])[tx];
        #pragma unroll
        for (int r = 0; r < 8; r++) {
            float x = Xs[(ty * 8 + r) * D + k];
            acc[r][0] = fmaf(x, w.x, acc[r][0]);
            acc[r][1] = fmaf(x, w.y, acc[r][1]);
            acc[r][2] = fmaf(x, w.z, acc[r][2]);
            acc[r][3] = fmaf(x, w.w, acc[r][3]);
        }
    }

    float4 bias = reinterpret_cast<const float4*>(b)[tx];
    #pragma unroll
    for (int r = 0; r < 8; r++) {
        int gr = row0 + ty * 8 + r;
        if (gr < n) {
            float4 o;
            o.x = acc[r][0] + bias.x;
            o.y = acc[r][1] + bias.y;
            o.z = acc[r][2] + bias.z;
            o.w = acc[r][3] + bias.w;
            reinterpret_cast<float4*>(&Y[gr * D])[tx] = o;
        }
    }
}

// ---------------- kernel 2: edge gather / gate / scatter ---------------------
// one warp per edge, lane handles features lane*4..lane*4+3
__global__ __launch_bounds__(256) void edge_kernel(
    const int* __restrict__ src, const int* __restrict__ dst, int E)
{
    int gwarp = (blockIdx.x * blockDim.x + threadIdx.x) >> 5;
    int lane  = threadIdx.x & 31;
    if (gwarp >= E) return;

    int s = src[gwarp];
    int t = dst[gwarp];
    int off = lane * 4;

    float4 dv = *reinterpret_cast<const float4*>(&g_DX[s * D + off]);
    float4 ev = *reinterpret_cast<const float4*>(&g_EX[t * D + off]);
    float4 bv = *reinterpret_cast<const float4*>(&g_BX[s * D + off]);

    float4 sg;
    sg.x = sigmoidf_fast(dv.x + ev.x);
    sg.y = sigmoidf_fast(dv.y + ev.y);
    sg.z = sigmoidf_fast(dv.z + ev.z);
    sg.w = sigmoidf_fast(dv.w + ev.w);

    float4 nm;
    nm.x = sg.x * bv.x;
    nm.y = sg.y * bv.y;
    nm.z = sg.z * bv.z;
    nm.w = sg.w * bv.w;

    red_add_v4(&g_num[t * D + off], nm);
    red_add_v4(&g_den[t * D + off], sg);
    if (lane == 0) atomicAdd(&g_deg[t], 1.0f);
}

// ---------------- kernel 3: per-node H + column partial sums -----------------
__global__ __launch_bounds__(128) void node_kernel(
    const float* __restrict__ X, int n, float inv_n)
{
    int d = threadIdx.x;
    float s = 0.0f, sq = 0.0f;
    for (int node = blockIdx.x; node < n; node += gridDim.x) {
        int idx = node * D + d;
        float h;
        if (g_deg[node] > 0.0f) {
            h = g_AX[idx] + g_num[idx] / g_den[idx];
        } else {
            h = X[idx];
        }
        h *= inv_n;
        g_H[idx] = h;
        s  += h;
        sq += h * h;
    }
    atomicAdd(&g_colsum[d], s);
    atomicAdd(&g_colsq[d], sq);
}

// ---------------- kernel 4: BN stats -> scale/shift --------------------------
__global__ void stats_kernel(const float* __restrict__ gamma,
                             const float* __restrict__ beta, float inv_n)
{
    int d = threadIdx.x;
    float mean = g_colsum[d] * inv_n;
    float var  = g_colsq[d] * inv_n - mean * mean;
    float istd = rsqrtf(var + 1e-5f);
    float sc   = istd * gamma[d];
    g_scale[d] = sc;
    g_shift[d] = beta[d] - mean * sc;
}

// ---------------- kernel 5: epilogue  out = X + relu(H*scale + shift) --------
__global__ __launch_bounds__(256) void final_kernel(
    const float* __restrict__ X, float* __restrict__ out, int n)
{
    __shared__ float sc[D];
    __shared__ float sh[D];
    if (threadIdx.x < D) {
        sc[threadIdx.x] = g_scale[threadIdx.x];
        sh[threadIdx.x] = g_shift[threadIdx.x];
    }
    __syncthreads();

    int total4 = n * (D / 4);
    const float4* X4 = reinterpret_cast<const float4*>(X);
    const float4* H4 = reinterpret_cast<const float4*>(g_H);
    float4* O4 = reinterpret_cast<float4*>(out);

    int tid = blockIdx.x * blockDim.x + threadIdx.x;
    int stride = gridDim.x * blockDim.x;
    for (int i = tid; i < total4; i += stride) {
        int d = (i & (D / 4 - 1)) * 4;
        float4 h = H4[i];
        float4 x = X4[i];
        float4 o;
        o.x = x.x + fmaxf(0.0f, fmaf(h.x, sc[d + 0], sh[d + 0]));
        o.y = x.y + fmaxf(0.0f, fmaf(h.y, sc[d + 1], sh[d + 1]));
        o.z = x.z + fmaxf(0.0f, fmaf(h.z, sc[d + 2], sh[d + 2]));
        o.w = x.w + fmaxf(0.0f, fmaf(h.w, sc[d + 3], sh[d + 3]));
        O4[i] = o;
    }
}

// ---------------- launch -----------------------------------------------------
extern "C" void kernel_launch(void* const* d_in, const int* in_sizes, int n_in,
                              void* d_out, int out_size)
{
    const float* X     = (const float*)d_in[0];
    const float* W_A   = (const float*)d_in[1];
    const float* b_A   = (const float*)d_in[2];
    const float* W_B   = (const float*)d_in[3];
    const float* b_B   = (const float*)d_in[4];
    const float* W_D   = (const float*)d_in[5];
    const float* b_D   = (const float*)d_in[6];
    const float* W_E   = (const float*)d_in[7];
    const float* b_E   = (const float*)d_in[8];
    const float* gamma = (const float*)d_in[9];
    const float* beta  = (const float*)d_in[10];
    const int*   src   = (const int*)d_in[11];
    const int*   dst   = (const int*)d_in[12];

    const int n = in_sizes[0] / D;
    const int E = in_sizes[11];
    const float inv_n = 1.0f / (float)n;

    // zero accumulators
    zero_kernel<<<1024, 256>>>(n);

    // fused 4-way GEMM (96KB dynamic smem)
    static const int smem_bytes = (64 * D + D * D) * (int)sizeof(float);
    cudaFuncSetAttribute(gemm4_kernel,
                         cudaFuncAttributeMaxDynamicSharedMemorySize, smem_bytes);
    dim3 ggrid((n + 63) / 64, 4);
    gemm4_kernel<<<ggrid, 256, smem_bytes>>>(X, W_A, b_A, W_B, b_B,
                                             W_D, b_D, W_E, b_E, n);

    // edge phase: one warp per edge
    int eblocks = (E + 7) / 8; // 8 warps per 256-thread block
    edge_kernel<<<eblocks, 256>>>(src, dst, E);

    // node phase + column partials
    node_kernel<<<592, 128>>>(X, n, inv_n);

    // BN stats
    stats_kernel<<<1, D>>>(gamma, beta, inv_n);

    // epilogue
    final_kernel<<<1024, 256>>>(X, (float*)d_out, n);
}

// round 2
// speedup vs baseline: 1.6997x; 1.6997x over previous
#include <cuda_runtime.h>
#include <cstdint>

#define D 128
#define MAXN 50000
#define MAXE 800000
#define SCAN_BLK 1024

// ---------------- scratch (device globals; no allocations allowed) ----------
__device__ float g_AX[MAXN * D];
__device__ float g_BX[MAXN * D];
__device__ float g_DX[MAXN * D];
__device__ float g_EX[MAXN * D];
__device__ float g_H [MAXN * D];
__device__ float g_WT[4 * D * D];        // transposed + tf32-rounded weights [n][k]
__device__ int   g_cnt[MAXN];
__device__ int   g_off[MAXN + 1];
__device__ int   g_csr[MAXE];
__device__ int   g_bsum[64];
__device__ int   g_bpre[64];
__device__ float g_colsum[D];
__device__ float g_colsq [D];
__device__ float g_scale [D];
__device__ float g_shift [D];

// ---------------- helpers ----------------------------------------------------
__device__ __forceinline__ float sigmoidf_fast(float x) {
    return 1.0f / (1.0f + __expf(-x));
}
__device__ __forceinline__ uint32_t f2tf32(float v) {
    uint32_t r;
    asm("cvt.rna.tf32.f32 %0, %1;" : "=r"(r) : "f"(v));
    return r;
}

// ---------------- kernel: zero counters + BN partials -------------------------
__global__ void zero_kernel(int n) {
    int tid = blockIdx.x * blockDim.x + threadIdx.x;
    int stride = gridDim.x * blockDim.x;
    for (int i = tid; i < n; i += stride) g_cnt[i] = 0;
    if (tid < D) { g_colsum[tid] = 0.0f; g_colsq[tid] = 0.0f; }
}

// ---------------- kernel: transpose + tf32-round the 4 weight matrices --------
// g_WT[mat][n*D + k] = tf32(W[k*D + n]).  grid (4,4,4), block (32,8)
__global__ void prepw_kernel(const float* __restrict__ WA, const float* __restrict__ WB,
                             const float* __restrict__ WD, const float* __restrict__ WE)
{
    __shared__ float t[32][33];
    const float* W;
    switch (blockIdx.z) {
        case 0:  W = WA; break;
        case 1:  W = WB; break;
        case 2:  W = WD; break;
        default: W = WE; break;
    }
    int n0 = blockIdx.x * 32;
    int k0 = blockIdx.y * 32;
    for (int i = threadIdx.y; i < 32; i += 8)
        t[i][threadIdx.x] = W[(k0 + i) * D + n0 + threadIdx.x];  // t[kl][nl]
    __syncthreads();
    float* out = g_WT + blockIdx.z * D * D;
    for (int i = threadIdx.y; i < 32; i += 8) {
        float v = t[threadIdx.x][i];                             // W[k0+tx][n0+i]
        out[(n0 + i) * D + k0 + threadIdx.x] = __uint_as_float(f2tf32(v));
    }
}

// ---------------- kernel: histogram of dst -----------------------------------
__global__ void hist_kernel(const int* __restrict__ dst, int E) {
    int e = blockIdx.x * blockDim.x + threadIdx.x;
    if (e < E) atomicAdd(&g_cnt[dst[e]], 1);
}

// ---------------- scan kernels: exclusive prefix over g_cnt -> g_off ----------
__global__ void scan1_kernel(int n) {
    __shared__ int s[SCAN_BLK];
    int tid = threadIdx.x;
    int i = blockIdx.x * SCAN_BLK + tid;
    s[tid] = (i < n) ? g_cnt[i] : 0;
    __syncthreads();
    for (int d = SCAN_BLK / 2; d > 0; d >>= 1) {
        if (tid < d) s[tid] += s[tid + d];
        __syncthreads();
    }
    if (tid == 0) g_bsum[blockIdx.x] = s[0];
}

__global__ void scan2_kernel(int nblk, int n) {
    __shared__ int s[64];
    int tid = threadIdx.x;
    int v = (tid < nblk) ? g_bsum[tid] : 0;
    s[tid] = v;
    __syncthreads();
    for (int d = 1; d < 64; d <<= 1) {
        int t = (tid >= d) ? s[tid - d] : 0;
        __syncthreads();
        s[tid] += t;
        __syncthreads();
    }
    if (tid < nblk) g_bpre[tid] = s[tid] - v;
    if (tid == 63) g_off[n] = s[63];
}

__global__ void scan3_kernel(int n) {
    __shared__ int s[SCAN_BLK];
    int tid = threadIdx.x;
    int i = blockIdx.x * SCAN_BLK + tid;
    int v = (i < n) ? g_cnt[i] : 0;
    s[tid] = v;
    __syncthreads();
    for (int d = 1; d < SCAN_BLK; d <<= 1) {
        int t = (tid >= d) ? s[tid - d] : 0;
        __syncthreads();
        s[tid] += t;
        __syncthreads();
    }
    if (i < n) {
        g_off[i] = g_bpre[blockIdx.x] + s[tid] - v;  // exclusive
        g_cnt[i] = 0;                                // reset as scatter cursor
    }
}

// ---------------- kernel: scatter edges into CSR order ------------------------
__global__ void scatter_kernel(const int* __restrict__ src, const int* __restrict__ dst, int E) {
    int e = blockIdx.x * blockDim.x + threadIdx.x;
    if (e < E) {
        int d0 = dst[e];
        int pos = g_off[d0] + atomicAdd(&g_cnt[d0], 1);
        g_csr[pos] = src[e];
    }
}

// ---------------- kernel: tf32 tensor GEMM  Y = X @ W + b --------------------
// block: 256 threads (8 warps), tile 128(M) x 128(N), full K=128 in smem.
// blockIdx.y selects matrix. Warp w owns M rows [w*16, w*16+16), all N.
#define SPAD 132   // 128 + 4 float pad -> conflict-free frag LDS
__global__ __launch_bounds__(256, 1) void gemm_kernel(
    const float* __restrict__ X,
    const float* __restrict__ bA, const float* __restrict__ bB,
    const float* __restrict__ bD, const float* __restrict__ bE,
    int n)
{
    extern __shared__ float smem[];
    float* Xs = smem;             // [128][SPAD]
    float* Ws = smem + 128 * SPAD;

    const float* bias; float* Y;
    switch (blockIdx.y) {
        case 0:  bias = bA; Y = g_AX; break;
        case 1:  bias = bB; Y = g_BX; break;
        case 2:  bias = bD; Y = g_DX; break;
        default: bias = bE; Y = g_EX; break;
    }
    const float* WT = g_WT + blockIdx.y * D * D;   // [n][k], pre-rounded

    const int tid  = threadIdx.x;
    const int row0 = blockIdx.x * 128;

    // load W^T tile (already tf32-rounded): 128 x 32 float4
    {
        const float4* Wg = reinterpret_cast<const float4*>(WT);
        #pragma unroll
        for (int i = 0; i < 16; i++) {
            int f  = tid + i * 256;       // [0,4096)
            int r  = f >> 5;
            int c4 = f & 31;
            *reinterpret_cast<float4*>(&Ws[r * SPAD + c4 * 4]) = Wg[f];
        }
    }
    // load X tile with tf32 rounding
    {
        const float4* Xg = reinterpret_cast<const float4*>(X);
        #pragma unroll
        for (int i = 0; i < 16; i++) {
            int f  = tid + i * 256;
            int r  = f >> 5;
            int c4 = f & 31;
            int gr = row0 + r;
            float4 v = make_float4(0.f, 0.f, 0.f, 0.f);
            if (gr < n) v = Xg[gr * 32 + c4];
            v.x = __uint_as_float(f2tf32(v.x));
            v.y = __uint_as_float(f2tf32(v.y));
            v.z = __uint_as_float(f2tf32(v.z));
            v.w = __uint_as_float(f2tf32(v.w));
            *reinterpret_cast<float4*>(&Xs[r * SPAD + c4 * 4]) = v;
        }
    }
    __syncthreads();

    const int lane = tid & 31;
    const int warp = tid >> 5;
    const int m0   = warp * 16;
    const int r    = lane >> 2;
    const int c    = lane & 3;

    float acc[16][4];
    #pragma unroll
    for (int nt = 0; nt < 16; nt++)
        #pragma unroll
        for (int j = 0; j < 4; j++) acc[nt][j] = 0.0f;

    for (int k0 = 0; k0 < D; k0 += 8) {
        uint32_t a0 = __float_as_uint(Xs[(m0 + r    ) * SPAD + k0 + c    ]);
        uint32_t a1 = __float_as_uint(Xs[(m0 + r + 8) * SPAD + k0 + c    ]);
        uint32_t a2 = __float_as_uint(Xs[(m0 + r    ) * SPAD + k0 + c + 4]);
        uint32_t a3 = __float_as_uint(Xs[(m0 + r + 8) * SPAD + k0 + c + 4]);
        #pragma unroll
        for (int nt = 0; nt < 16; nt++) {
            uint32_t b0 = __float_as_uint(Ws[(nt * 8 + r) * SPAD + k0 + c    ]);
            uint32_t b1 = __float_as_uint(Ws[(nt * 8 + r) * SPAD + k0 + c + 4]);
            asm volatile(
                "mma.sync.aligned.m16n8k8.row.col.f32.tf32.tf32.f32 "
                "{%0,%1,%2,%3}, {%4,%5,%6,%7}, {%8,%9}, {%0,%1,%2,%3};"
                : "+f"(acc[nt][0]), "+f"(acc[nt][1]), "+f"(acc[nt][2]), "+f"(acc[nt][3])
                : "r"(a0), "r"(a1), "r"(a2), "r"(a3), "r"(b0), "r"(b1));
        }
    }

    const int gr0 = row0 + m0 + r;
    const int gr1 = gr0 + 8;
    #pragma unroll
    for (int nt = 0; nt < 16; nt++) {
        int col = nt * 8 + c * 2;
        float2 bv = *reinterpret_cast<const float2*>(&bias[col]);
        if (gr0 < n) {
            float2 o = make_float2(acc[nt][0] + bv.x, acc[nt][1] + bv.y);
            *reinterpret_cast<float2*>(&Y[gr0 * D + col]) = o;
        }
        if (gr1 < n) {
            float2 o = make_float2(acc[nt][2] + bv.x, acc[nt][3] + bv.y);
            *reinterpret_cast<float2*>(&Y[gr1 * D + col]) = o;
        }
    }
}

// ---------------- kernel: per-node aggregation + H + BN partials --------------
// one warp per node (grid-stride). lane owns features [lane*4, lane*4+4).
__global__ __launch_bounds__(256) void agg_kernel(const float* __restrict__ X,
                                                  int n, float inv_n)
{
    __shared__ float ssum[D];
    __shared__ float ssq [D];
    const int tid = threadIdx.x;
    if (tid < D) { ssum[tid] = 0.0f; ssq[tid] = 0.0f; }
    __syncthreads();

    const int lane = tid & 31;
    const int warp = tid >> 5;
    const int off  = lane * 4;
    const int gw   = blockIdx.x * 8 + warp;
    const int nw   = gridDim.x * 8;

    float4 csum = make_float4(0.f, 0.f, 0.f, 0.f);
    float4 csq  = make_float4(0.f, 0.f, 0.f, 0.f);

    for (int node = gw; node < n; node += nw) {
        int beg = g_off[node];
        int end = g_off[node + 1];
        int base = node * D + off;
        float4 h;
        if (end > beg) {
            float4 ev = *reinterpret_cast<const float4*>(&g_EX[base]);
            float4 num = make_float4(0.f, 0.f, 0.f, 0.f);
            float4 den = make_float4(0.f, 0.f, 0.f, 0.f);
            for (int j = beg; j < end; j++) {
                int s = g_csr[j];
                float4 dv = *reinterpret_cast<const float4*>(&g_DX[s * D + off]);
                float4 bv = *reinterpret_cast<const float4*>(&g_BX[s * D + off]);
                float4 sg;
                sg.x = sigmoidf_fast(dv.x + ev.x);
                sg.y = sigmoidf_fast(dv.y + ev.y);
                sg.z = sigmoidf_fast(dv.z + ev.z);
                sg.w = sigmoidf_fast(dv.w + ev.w);
                num.x = fmaf(sg.x, bv.x, num.x);
                num.y = fmaf(sg.y, bv.y, num.y);
                num.z = fmaf(sg.z, bv.z, num.z);
                num.w = fmaf(sg.w, bv.w, num.w);
                den.x += sg.x; den.y += sg.y; den.z += sg.z; den.w += sg.w;
            }
            float4 ax = *reinterpret_cast<const float4*>(&g_AX[base]);
            h.x = (ax.x + num.x / den.x) * inv_n;
            h.y = (ax.y + num.y / den.y) * inv_n;
            h.z = (ax.z + num.z / den.z) * inv_n;
            h.w = (ax.w + num.w / den.w) * inv_n;
        } else {
            float4 xv = *reinterpret_cast<const float4*>(&X[base]);
            h.x = xv.x * inv_n;
            h.y = xv.y * inv_n;
            h.z = xv.z * inv_n;
            h.w = xv.w * inv_n;
        }
        *reinterpret_cast<float4*>(&g_H[base]) = h;
        csum.x += h.x; csum.y += h.y; csum.z += h.z; csum.w += h.w;
        csq.x  = fmaf(h.x, h.x, csq.x);
        csq.y  = fmaf(h.y, h.y, csq.y);
        csq.z  = fmaf(h.z, h.z, csq.z);
        csq.w  = fmaf(h.w, h.w, csq.w);
    }

    atomicAdd(&ssum[off + 0], csum.x); atomicAdd(&ssum[off + 1], csum.y);
    atomicAdd(&ssum[off + 2], csum.z); atomicAdd(&ssum[off + 3], csum.w);
    atomicAdd(&ssq [off + 0], csq.x);  atomicAdd(&ssq [off + 1], csq.y);
    atomicAdd(&ssq [off + 2], csq.z);  atomicAdd(&ssq [off + 3], csq.w);
    __syncthreads();
    if (tid < D) {
        atomicAdd(&g_colsum[tid], ssum[tid]);
        atomicAdd(&g_colsq [tid], ssq [tid]);
    }
}

// ---------------- kernel: BN stats -> scale/shift ------------------------------
__global__ void stats_kernel(const float* __restrict__ gamma,
                             const float* __restrict__ beta, float inv_n)
{
    int d = threadIdx.x;
    float mean = g_colsum[d] * inv_n;
    float var  = g_colsq[d] * inv_n - mean * mean;
    float istd = rsqrtf(var + 1e-5f);
    float sc   = istd * gamma[d];
    g_scale[d] = sc;
    g_shift[d] = beta[d] - mean * sc;
}

// ---------------- kernel: epilogue  out = X + relu(H*scale + shift) -----------
__global__ __launch_bounds__(256) void final_kernel(
    const float* __restrict__ X, float* __restrict__ out, int n)
{
    __shared__ float sc[D];
    __shared__ float sh[D];
    if (threadIdx.x < D) {
        sc[threadIdx.x] = g_scale[threadIdx.x];
        sh[threadIdx.x] = g_shift[threadIdx.x];
    }
    __syncthreads();

    int total4 = n * (D / 4);
    const float4* X4 = reinterpret_cast<const float4*>(X);
    const float4* H4 = reinterpret_cast<const float4*>(g_H);
    float4* O4 = reinterpret_cast<float4*>(out);

    int tid = blockIdx.x * blockDim.x + threadIdx.x;
    int stride = gridDim.x * blockDim.x;
    for (int i = tid; i < total4; i += stride) {
        int d = (i & 31) * 4;
        float4 h = H4[i];
        float4 x = X4[i];
        float4 o;
        o.x = x.x + fmaxf(0.0f, fmaf(h.x, sc[d + 0], sh[d + 0]));
        o.y = x.y + fmaxf(0.0f, fmaf(h.y, sc[d + 1], sh[d + 1]));
        o.z = x.z + fmaxf(0.0f, fmaf(h.z, sc[d + 2], sh[d + 2]));
        o.w = x.w + fmaxf(0.0f, fmaf(h.w, sc[d + 3], sh[d + 3]));
        O4[i] = o;
    }
}

// ---------------- launch -----------------------------------------------------
extern "C" void kernel_launch(void* const* d_in, const int* in_sizes, int n_in,
                              void* d_out, int out_size)
{
    const float* X     = (const float*)d_in[0];
    const float* W_A   = (const float*)d_in[1];
    const float* b_A   = (const float*)d_in[2];
    const float* W_B   = (const float*)d_in[3];
    const float* b_B   = (const float*)d_in[4];
    const float* W_D   = (const float*)d_in[5];
    const float* b_D   = (const float*)d_in[6];
    const float* W_E   = (const float*)d_in[7];
    const float* b_E   = (const float*)d_in[8];
    const float* gamma = (const float*)d_in[9];
    const float* beta  = (const float*)d_in[10];
    const int*   src   = (const int*)d_in[11];
    const int*   dst   = (const int*)d_in[12];

    const int n = in_sizes[0] / D;
    const int E = in_sizes[11];
    const float inv_n = 1.0f / (float)n;
    const int nblk = (n + SCAN_BLK - 1) / SCAN_BLK;

    zero_kernel<<<128, 256>>>(n);

    prepw_kernel<<<dim3(4, 4, 4), dim3(32, 8)>>>(W_A, W_B, W_D, W_E);

    hist_kernel<<<(E + 255) / 256, 256>>>(dst, E);
    scan1_kernel<<<nblk, SCAN_BLK>>>(n);
    scan2_kernel<<<1, 64>>>(nblk, n);
    scan3_kernel<<<nblk, SCAN_BLK>>>(n);
    scatter_kernel<<<(E + 255) / 256, 256>>>(src, dst, E);

    static const int smem_bytes = 2 * 128 * SPAD * (int)sizeof(float);
    cudaFuncSetAttribute(gemm_kernel,
                         cudaFuncAttributeMaxDynamicSharedMemorySize, smem_bytes);
    dim3 ggrid((n + 127) / 128, 4);
    gemm_kernel<<<ggrid, 256, smem_bytes>>>(X, b_A, b_B, b_D, b_E, n);

    agg_kernel<<<1184, 256>>>(X, n, inv_n);

    stats_kernel<<<1, D>>>(gamma, beta, inv_n);

    final_kernel<<<1024, 256>>>(X, (float*)d_out, n);
}

// round 3
// speedup vs baseline: 1.7403x; 1.0239x over previous
#include <cuda_runtime.h>
#include <cuda_fp16.h>
#include <cstdint>

#define D 128
#define MAXN 50000
#define MAXE 800000
#define SCAN_BLK 1024

// ---------------- scratch (device globals; no allocations allowed) ----------
__device__ float  g_AX[MAXN * D];
__device__ __half g_BXh[MAXN * D];
__device__ __half g_DXh[MAXN * D];
__device__ __half g_EXh[MAXN * D];
__device__ float  g_H [MAXN * D];
__device__ float  g_WT[4 * D * D];        // transposed + tf32-rounded weights [n][k]
__device__ int    g_cnt[MAXN];
__device__ int    g_off[MAXN + 1];
__device__ int    g_csr[MAXE];
__device__ int    g_bsum[64];
__device__ int    g_bpre[64];
__device__ float  g_colsum[D];
__device__ float  g_colsq [D];
__device__ float  g_scale [D];
__device__ float  g_shift [D];

// ---------------- static stream/event context (created at load, pre-capture) -
namespace {
struct Ctx {
    cudaStream_t sb;
    cudaEvent_t ev_fork, ev_join;
    Ctx() {
        cudaStreamCreateWithFlags(&sb, cudaStreamNonBlocking);
        cudaEventCreateWithFlags(&ev_fork, cudaEventDisableTiming);
        cudaEventCreateWithFlags(&ev_join, cudaEventDisableTiming);
    }
};
Ctx g_ctx;
}

// ---------------- helpers ----------------------------------------------------
__device__ __forceinline__ float sigmoidf_fast(float x) {
    return 1.0f / (1.0f + __expf(-x));
}
__device__ __forceinline__ uint32_t f2tf32(float v) {
    uint32_t r;
    asm("cvt.rna.tf32.f32 %0, %1;" : "=r"(r) : "f"(v));
    return r;
}

// ---------------- kernel: zero counters + BN partials -------------------------
__global__ void zero_kernel(int n) {
    int tid = blockIdx.x * blockDim.x + threadIdx.x;
    int stride = gridDim.x * blockDim.x;
    for (int i = tid; i < n; i += stride) g_cnt[i] = 0;
    if (tid < D) { g_colsum[tid] = 0.0f; g_colsq[tid] = 0.0f; }
}

// ---------------- kernel: transpose + tf32-round the 4 weight matrices --------
__global__ void prepw_kernel(const float* __restrict__ WA, const float* __restrict__ WB,
                             const float* __restrict__ WD, const float* __restrict__ WE)
{
    __shared__ float t[32][33];
    const float* W;
    switch (blockIdx.z) {
        case 0:  W = WA; break;
        case 1:  W = WB; break;
        case 2:  W = WD; break;
        default: W = WE; break;
    }
    int n0 = blockIdx.x * 32;
    int k0 = blockIdx.y * 32;
    for (int i = threadIdx.y; i < 32; i += 8)
        t[i][threadIdx.x] = W[(k0 + i) * D + n0 + threadIdx.x];
    __syncthreads();
    float* out = g_WT + blockIdx.z * D * D;
    for (int i = threadIdx.y; i < 32; i += 8) {
        float v = t[threadIdx.x][i];
        out[(n0 + i) * D + k0 + threadIdx.x] = __uint_as_float(f2tf32(v));
    }
}

// ---------------- kernel: histogram of dst -----------------------------------
__global__ void hist_kernel(const int* __restrict__ dst, int E) {
    int e = blockIdx.x * blockDim.x + threadIdx.x;
    if (e < E) atomicAdd(&g_cnt[dst[e]], 1);
}

// ---------------- scan kernels: exclusive prefix over g_cnt -> g_off ----------
__global__ void scan1_kernel(int n) {
    __shared__ int s[SCAN_BLK];
    int tid = threadIdx.x;
    int i = blockIdx.x * SCAN_BLK + tid;
    s[tid] = (i < n) ? g_cnt[i] : 0;
    __syncthreads();
    for (int d = SCAN_BLK / 2; d > 0; d >>= 1) {
        if (tid < d) s[tid] += s[tid + d];
        __syncthreads();
    }
    if (tid == 0) g_bsum[blockIdx.x] = s[0];
}

__global__ void scan2_kernel(int nblk, int n) {
    __shared__ int s[64];
    int tid = threadIdx.x;
    int v = (tid < nblk) ? g_bsum[tid] : 0;
    s[tid] = v;
    __syncthreads();
    for (int d = 1; d < 64; d <<= 1) {
        int t = (tid >= d) ? s[tid - d] : 0;
        __syncthreads();
        s[tid] += t;
        __syncthreads();
    }
    if (tid < nblk) g_bpre[tid] = s[tid] - v;
    if (tid == 63) g_off[n] = s[63];
}

__global__ void scan3_kernel(int n) {
    __shared__ int s[SCAN_BLK];
    int tid = threadIdx.x;
    int i = blockIdx.x * SCAN_BLK + tid;
    int v = (i < n) ? g_cnt[i] : 0;
    s[tid] = v;
    __syncthreads();
    for (int d = 1; d < SCAN_BLK; d <<= 1) {
        int t = (tid >= d) ? s[tid - d] : 0;
        __syncthreads();
        s[tid] += t;
        __syncthreads();
    }
    if (i < n) {
        g_off[i] = g_bpre[blockIdx.x] + s[tid] - v;  // exclusive
        g_cnt[i] = 0;                                // reset as scatter cursor
    }
}

// ---------------- kernel: scatter edges into CSR order ------------------------
__global__ void scatter_kernel(const int* __restrict__ src, const int* __restrict__ dst, int E) {
    int e = blockIdx.x * blockDim.x + threadIdx.x;
    if (e < E) {
        int d0 = dst[e];
        int pos = g_off[d0] + atomicAdd(&g_cnt[d0], 1);
        g_csr[pos] = src[e];
    }
}

// ---------------- kernel: tf32 tensor GEMM  Y = X @ W + b --------------------
// y==0 writes fp32 g_AX; y in {1,2,3} writes fp16 g_BXh/g_DXh/g_EXh
#define SPAD 132
__global__ __launch_bounds__(256, 1) void gemm_kernel(
    const float* __restrict__ X,
    const float* __restrict__ bA, const float* __restrict__ bB,
    const float* __restrict__ bD, const float* __restrict__ bE,
    int n)
{
    extern __shared__ float smem[];
    float* Xs = smem;             // [128][SPAD]
    float* Ws = smem + 128 * SPAD;

    const float* bias; float* Yf = nullptr; __half* Yh = nullptr;
    switch (blockIdx.y) {
        case 0:  bias = bA; Yf = g_AX;  break;
        case 1:  bias = bB; Yh = g_BXh; break;
        case 2:  bias = bD; Yh = g_DXh; break;
        default: bias = bE; Yh = g_EXh; break;
    }
    const float* WT = g_WT + blockIdx.y * D * D;

    const int tid  = threadIdx.x;
    const int row0 = blockIdx.x * 128;

    {
        const float4* Wg = reinterpret_cast<const float4*>(WT);
        #pragma unroll
        for (int i = 0; i < 16; i++) {
            int f  = tid + i * 256;
            int r  = f >> 5;
            int c4 = f & 31;
            *reinterpret_cast<float4*>(&Ws[r * SPAD + c4 * 4]) = Wg[f];
        }
    }
    {
        const float4* Xg = reinterpret_cast<const float4*>(X);
        #pragma unroll
        for (int i = 0; i < 16; i++) {
            int f  = tid + i * 256;
            int r  = f >> 5;
            int c4 = f & 31;
            int gr = row0 + r;
            float4 v = make_float4(0.f, 0.f, 0.f, 0.f);
            if (gr < n) v = Xg[gr * 32 + c4];
            v.x = __uint_as_float(f2tf32(v.x));
            v.y = __uint_as_float(f2tf32(v.y));
            v.z = __uint_as_float(f2tf32(v.z));
            v.w = __uint_as_float(f2tf32(v.w));
            *reinterpret_cast<float4*>(&Xs[r * SPAD + c4 * 4]) = v;
        }
    }
    __syncthreads();

    const int lane = tid & 31;
    const int warp = tid >> 5;
    const int m0   = warp * 16;
    const int r    = lane >> 2;
    const int c    = lane & 3;

    float acc[16][4];
    #pragma unroll
    for (int nt = 0; nt < 16; nt++)
        #pragma unroll
        for (int j = 0; j < 4; j++) acc[nt][j] = 0.0f;

    for (int k0 = 0; k0 < D; k0 += 8) {
        uint32_t a0 = __float_as_uint(Xs[(m0 + r    ) * SPAD + k0 + c    ]);
        uint32_t a1 = __float_as_uint(Xs[(m0 + r + 8) * SPAD + k0 + c    ]);
        uint32_t a2 = __float_as_uint(Xs[(m0 + r    ) * SPAD + k0 + c + 4]);
        uint32_t a3 = __float_as_uint(Xs[(m0 + r + 8) * SPAD + k0 + c + 4]);
        #pragma unroll
        for (int nt = 0; nt < 16; nt++) {
            uint32_t b0 = __float_as_uint(Ws[(nt * 8 + r) * SPAD + k0 + c    ]);
            uint32_t b1 = __float_as_uint(Ws[(nt * 8 + r) * SPAD + k0 + c + 4]);
            asm volatile(
                "mma.sync.aligned.m16n8k8.row.col.f32.tf32.tf32.f32 "
                "{%0,%1,%2,%3}, {%4,%5,%6,%7}, {%8,%9}, {%0,%1,%2,%3};"
                : "+f"(acc[nt][0]), "+f"(acc[nt][1]), "+f"(acc[nt][2]), "+f"(acc[nt][3])
                : "r"(a0), "r"(a1), "r"(a2), "r"(a3), "r"(b0), "r"(b1));
        }
    }

    const int gr0 = row0 + m0 + r;
    const int gr1 = gr0 + 8;
    #pragma unroll
    for (int nt = 0; nt < 16; nt++) {
        int col = nt * 8 + c * 2;
        float2 bv = *reinterpret_cast<const float2*>(&bias[col]);
        float2 o0 = make_float2(acc[nt][0] + bv.x, acc[nt][1] + bv.y);
        float2 o1 = make_float2(acc[nt][2] + bv.x, acc[nt][3] + bv.y);
        if (Yf) {
            if (gr0 < n) *reinterpret_cast<float2*>(&Yf[gr0 * D + col]) = o0;
            if (gr1 < n) *reinterpret_cast<float2*>(&Yf[gr1 * D + col]) = o1;
        } else {
            if (gr0 < n) *reinterpret_cast<__half2*>(&Yh[gr0 * D + col]) = __floats2half2_rn(o0.x, o0.y);
            if (gr1 < n) *reinterpret_cast<__half2*>(&Yh[gr1 * D + col]) = __floats2half2_rn(o1.x, o1.y);
        }
    }
}

// ---------------- kernel: per-node aggregation + H + BN partials --------------
// one warp per node (grid-stride). lane owns features [lane*4, lane*4+4).
__device__ __forceinline__ float4 h4_to_f4(uint2 u) {
    __half2 lo = *reinterpret_cast<__half2*>(&u.x);
    __half2 hi = *reinterpret_cast<__half2*>(&u.y);
    float2 a = __half22float2(lo);
    float2 b = __half22float2(hi);
    return make_float4(a.x, a.y, b.x, b.y);
}

__global__ __launch_bounds__(256) void agg_kernel(const float* __restrict__ X,
                                                  int n, float inv_n)
{
    __shared__ float ssum[D];
    __shared__ float ssq [D];
    const int tid = threadIdx.x;
    if (tid < D) { ssum[tid] = 0.0f; ssq[tid] = 0.0f; }
    __syncthreads();

    const int lane = tid & 31;
    const int warp = tid >> 5;
    const int off  = lane * 4;
    const int gw   = blockIdx.x * 8 + warp;
    const int nw   = gridDim.x * 8;

    float4 csum = make_float4(0.f, 0.f, 0.f, 0.f);
    float4 csq  = make_float4(0.f, 0.f, 0.f, 0.f);

    for (int node = gw; node < n; node += nw) {
        int beg = g_off[node];
        int end = g_off[node + 1];
        int base = node * D + off;
        float4 h;
        if (end > beg) {
            float4 ev = h4_to_f4(*reinterpret_cast<const uint2*>(&g_EXh[base]));
            float4 num = make_float4(0.f, 0.f, 0.f, 0.f);
            float4 den = make_float4(0.f, 0.f, 0.f, 0.f);
            int j = beg;
            // 2-way unrolled: two independent gathers in flight
            for (; j + 1 < end; j += 2) {
                int s0 = g_csr[j];
                int s1 = g_csr[j + 1];
                float4 dv0 = h4_to_f4(*reinterpret_cast<const uint2*>(&g_DXh[s0 * D + off]));
                float4 bv0 = h4_to_f4(*reinterpret_cast<const uint2*>(&g_BXh[s0 * D + off]));
                float4 dv1 = h4_to_f4(*reinterpret_cast<const uint2*>(&g_DXh[s1 * D + off]));
                float4 bv1 = h4_to_f4(*reinterpret_cast<const uint2*>(&g_BXh[s1 * D + off]));
                float4 sg0, sg1;
                sg0.x = sigmoidf_fast(dv0.x + ev.x); sg1.x = sigmoidf_fast(dv1.x + ev.x);
                sg0.y = sigmoidf_fast(dv0.y + ev.y); sg1.y = sigmoidf_fast(dv1.y + ev.y);
                sg0.z = sigmoidf_fast(dv0.z + ev.z); sg1.z = sigmoidf_fast(dv1.z + ev.z);
                sg0.w = sigmoidf_fast(dv0.w + ev.w); sg1.w = sigmoidf_fast(dv1.w + ev.w);
                num.x = fmaf(sg0.x, bv0.x, fmaf(sg1.x, bv1.x, num.x));
                num.y = fmaf(sg0.y, bv0.y, fmaf(sg1.y, bv1.y, num.y));
                num.z = fmaf(sg0.z, bv0.z, fmaf(sg1.z, bv1.z, num.z));
                num.w = fmaf(sg0.w, bv0.w, fmaf(sg1.w, bv1.w, num.w));
                den.x += sg0.x + sg1.x; den.y += sg0.y + sg1.y;
                den.z += sg0.z + sg1.z; den.w += sg0.w + sg1.w;
            }
            if (j < end) {
                int s = g_csr[j];
                float4 dv = h4_to_f4(*reinterpret_cast<const uint2*>(&g_DXh[s * D + off]));
                float4 bv = h4_to_f4(*reinterpret_cast<const uint2*>(&g_BXh[s * D + off]));
                float4 sg;
                sg.x = sigmoidf_fast(dv.x + ev.x);
                sg.y = sigmoidf_fast(dv.y + ev.y);
                sg.z = sigmoidf_fast(dv.z + ev.z);
                sg.w = sigmoidf_fast(dv.w + ev.w);
                num.x = fmaf(sg.x, bv.x, num.x);
                num.y = fmaf(sg.y, bv.y, num.y);
                num.z = fmaf(sg.z, bv.z, num.z);
                num.w = fmaf(sg.w, bv.w, num.w);
                den.x += sg.x; den.y += sg.y; den.z += sg.z; den.w += sg.w;
            }
            float4 ax = *reinterpret_cast<const float4*>(&g_AX[base]);
            h.x = (ax.x + num.x / den.x) * inv_n;
            h.y = (ax.y + num.y / den.y) * inv_n;
            h.z = (ax.z + num.z / den.z) * inv_n;
            h.w = (ax.w + num.w / den.w) * inv_n;
        } else {
            float4 xv = *reinterpret_cast<const float4*>(&X[base]);
            h.x = xv.x * inv_n;
            h.y = xv.y * inv_n;
            h.z = xv.z * inv_n;
            h.w = xv.w * inv_n;
        }
        *reinterpret_cast<float4*>(&g_H[base]) = h;
        csum.x += h.x; csum.y += h.y; csum.z += h.z; csum.w += h.w;
        csq.x  = fmaf(h.x, h.x, csq.x);
        csq.y  = fmaf(h.y, h.y, csq.y);
        csq.z  = fmaf(h.z, h.z, csq.z);
        csq.w  = fmaf(h.w, h.w, csq.w);
    }

    atomicAdd(&ssum[off + 0], csum.x); atomicAdd(&ssum[off + 1], csum.y);
    atomicAdd(&ssum[off + 2], csum.z); atomicAdd(&ssum[off + 3], csum.w);
    atomicAdd(&ssq [off + 0], csq.x);  atomicAdd(&ssq [off + 1], csq.y);
    atomicAdd(&ssq [off + 2], csq.z);  atomicAdd(&ssq [off + 3], csq.w);
    __syncthreads();
    if (tid < D) {
        atomicAdd(&g_colsum[tid], ssum[tid]);
        atomicAdd(&g_colsq [tid], ssq [tid]);
    }
}

// ---------------- kernel: BN stats -> scale/shift ------------------------------
__global__ void stats_kernel(const float* __restrict__ gamma,
                             const float* __restrict__ beta, float inv_n)
{
    int d = threadIdx.x;
    float mean = g_colsum[d] * inv_n;
    float var  = g_colsq[d] * inv_n - mean * mean;
    float istd = rsqrtf(var + 1e-5f);
    float sc   = istd * gamma[d];
    g_scale[d] = sc;
    g_shift[d] = beta[d] - mean * sc;
}

// ---------------- kernel: epilogue  out = X + relu(H*scale + shift) -----------
__global__ __launch_bounds__(256) void final_kernel(
    const float* __restrict__ X, float* __restrict__ out, int n)
{
    __shared__ float sc[D];
    __shared__ float sh[D];
    if (threadIdx.x < D) {
        sc[threadIdx.x] = g_scale[threadIdx.x];
        sh[threadIdx.x] = g_shift[threadIdx.x];
    }
    __syncthreads();

    int total4 = n * (D / 4);
    const float4* X4 = reinterpret_cast<const float4*>(X);
    const float4* H4 = reinterpret_cast<const float4*>(g_H);
    float4* O4 = reinterpret_cast<float4*>(out);

    int tid = blockIdx.x * blockDim.x + threadIdx.x;
    int stride = gridDim.x * blockDim.x;
    for (int i = tid; i < total4; i += stride) {
        int d = (i & 31) * 4;
        float4 h = H4[i];
        float4 x = X4[i];
        float4 o;
        o.x = x.x + fmaxf(0.0f, fmaf(h.x, sc[d + 0], sh[d + 0]));
        o.y = x.y + fmaxf(0.0f, fmaf(h.y, sc[d + 1], sh[d + 1]));
        o.z = x.z + fmaxf(0.0f, fmaf(h.z, sc[d + 2], sh[d + 2]));
        o.w = x.w + fmaxf(0.0f, fmaf(h.w, sc[d + 3], sh[d + 3]));
        O4[i] = o;
    }
}

// ---------------- launch -----------------------------------------------------
extern "C" void kernel_launch(void* const* d_in, const int* in_sizes, int n_in,
                              void* d_out, int out_size)
{
    const float* X     = (const float*)d_in[0];
    const float* W_A   = (const float*)d_in[1];
    const float* b_A   = (const float*)d_in[2];
    const float* W_B   = (const float*)d_in[3];
    const float* b_B   = (const float*)d_in[4];
    const float* W_D   = (const float*)d_in[5];
    const float* b_D   = (const float*)d_in[6];
    const float* W_E   = (const float*)d_in[7];
    const float* b_E   = (const float*)d_in[8];
    const float* gamma = (const float*)d_in[9];
    const float* beta  = (const float*)d_in[10];
    const int*   src   = (const int*)d_in[11];
    const int*   dst   = (const int*)d_in[12];

    const int n = in_sizes[0] / D;
    const int E = in_sizes[11];
    const float inv_n = 1.0f / (float)n;
    const int nblk = (n + SCAN_BLK - 1) / SCAN_BLK;

    // fork: CSR build chain on side stream, GEMM path on main stream
    cudaEventRecord(g_ctx.ev_fork, 0);
    cudaStreamWaitEvent(g_ctx.sb, g_ctx.ev_fork, 0);

    zero_kernel<<<128, 256, 0, g_ctx.sb>>>(n);
    hist_kernel<<<(E + 255) / 256, 256, 0, g_ctx.sb>>>(dst, E);
    scan1_kernel<<<nblk, SCAN_BLK, 0, g_ctx.sb>>>(n);
    scan2_kernel<<<1, 64, 0, g_ctx.sb>>>(nblk, n);
    scan3_kernel<<<nblk, SCAN_BLK, 0, g_ctx.sb>>>(n);
    scatter_kernel<<<(E + 255) / 256, 256, 0, g_ctx.sb>>>(src, dst, E);
    cudaEventRecord(g_ctx.ev_join, g_ctx.sb);

    prepw_kernel<<<dim3(4, 4, 4), dim3(32, 8)>>>(W_A, W_B, W_D, W_E);

    static const int smem_bytes = 2 * 128 * SPAD * (int)sizeof(float);
    cudaFuncSetAttribute(gemm_kernel,
                         cudaFuncAttributeMaxDynamicSharedMemorySize, smem_bytes);
    dim3 ggrid((n + 127) / 128, 4);
    gemm_kernel<<<ggrid, 256, smem_bytes>>>(X, b_A, b_B, b_D, b_E, n);

    // join
    cudaStreamWaitEvent(0, g_ctx.ev_join, 0);

    agg_kernel<<<1184, 256>>>(X, n, inv_n);
    stats_kernel<<<1, D>>>(gamma, beta, inv_n);
    final_kernel<<<1024, 256>>>(X, (float*)d_out, n);
}